// round 1
// baseline (speedup 1.0000x reference)
#include <cuda_runtime.h>
#include <math.h>

#define N_NODES  50000
#define N_EDGES  800000
#define NODE_DIM 64
#define EDGE_DIM 32
#define HID      128

// Scratch: per-node precomputed rows [ns(128) | nd(128) | cs(128) | cd(128)]
__device__ float g_A[(size_t)N_NODES * 512];
// Folded edge-path weights
__device__ float g_Mn[32 * 128];
__device__ float g_Mc[32 * 128];
__device__ float g_bn[128];
__device__ float g_bc[128];

// ---------------------------------------------------------------------------
// K0: fold M_n = W_e2 @ W_n1[128:160], M_c = W_e2 @ W_c1[128:160],
//     bn' = b_n1 + b_e2 @ W_n1[128:160], bc' = b_c1 + b_e2 @ W_c1[128:160]
// ---------------------------------------------------------------------------
__global__ void k_fold(const float* __restrict__ We2, const float* __restrict__ be2,
                       const float* __restrict__ Wn1, const float* __restrict__ bn1,
                       const float* __restrict__ Wc1, const float* __restrict__ bc1) {
    int j = threadIdx.x;  // 0..127
    float bn = bn1[j], bc = bc1[j];
    for (int b = 0; b < 32; b++) {
        bn += be2[b] * Wn1[(128 + b) * 128 + j];
        bc += be2[b] * Wc1[(128 + b) * 128 + j];
    }
    g_bn[j] = bn;
    g_bc[j] = bc;
    for (int a = 0; a < 32; a++) {
        float sn = 0.f, sc = 0.f;
        for (int b = 0; b < 32; b++) {
            float w = We2[a * 32 + b];
            sn += w * Wn1[(128 + b) * 128 + j];
            sc += w * Wc1[(128 + b) * 128 + j];
        }
        g_Mn[a * 128 + j] = sn;
        g_Mc[a * 128 + j] = sc;
    }
}

// ---------------------------------------------------------------------------
// K1: per-node precompute  A[n] = [h@Wn1_src | h@Wn1_dst | h@Wc1_src | h@Wc1_dst]
// ---------------------------------------------------------------------------
#define NPB 8
__global__ void k_node(const float* __restrict__ h,
                       const float* __restrict__ Wn1,
                       const float* __restrict__ Wc1) {
    __shared__ float h_sh[NPB * 64];
    int node0 = blockIdx.x * NPB;
    for (int i = threadIdx.x; i < NPB * 64; i += 128) {
        int idx = node0 * 64 + i;
        h_sh[i] = (idx < N_NODES * 64) ? h[idx] : 0.f;
    }
    __syncthreads();
    int j = threadIdx.x;  // 0..127
    float ans[NPB], andv[NPB], acs[NPB], acd[NPB];
#pragma unroll
    for (int n = 0; n < NPB; n++) { ans[n] = 0.f; andv[n] = 0.f; acs[n] = 0.f; acd[n] = 0.f; }
#pragma unroll 4
    for (int k = 0; k < 64; k++) {
        float w0 = Wn1[k * 128 + j];
        float w1 = Wn1[(64 + k) * 128 + j];
        float w2 = Wc1[k * 128 + j];
        float w3 = Wc1[(64 + k) * 128 + j];
#pragma unroll
        for (int n = 0; n < NPB; n++) {
            float hv = h_sh[n * 64 + k];
            ans[n]  += hv * w0;
            andv[n] += hv * w1;
            acs[n]  += hv * w2;
            acd[n]  += hv * w3;
        }
    }
#pragma unroll
    for (int n = 0; n < NPB; n++) {
        int node = node0 + n;
        if (node < N_NODES) {
            size_t base = (size_t)node * 512;
            g_A[base + j]       = ans[n];
            g_A[base + 128 + j] = andv[n];
            g_A[base + 256 + j] = acs[n];
            g_A[base + 384 + j] = acd[n];
        }
    }
}

// ---------------------------------------------------------------------------
// K2: initialize output with (h, x) so edge kernel can atomically accumulate
// ---------------------------------------------------------------------------
__global__ void k_init(const float* __restrict__ h, const float* __restrict__ x,
                       float* __restrict__ out) {
    int nh = N_NODES * NODE_DIM;
    int tot = nh + N_NODES * 3;
    for (int i = blockIdx.x * blockDim.x + threadIdx.x; i < tot; i += gridDim.x * blockDim.x)
        out[i] = (i < nh) ? h[i] : x[i - nh];
}

// ---------------------------------------------------------------------------
// K3: edge kernel. One warp processes 4 edges per iteration.
// ---------------------------------------------------------------------------
__device__ __forceinline__ float silu1(float z) {
    return z * __fdividef(1.f, 1.f + __expf(-z));
}

__global__ void __launch_bounds__(256, 2)
k_edge(const float* __restrict__ dist,
       const int*   __restrict__ eidx,
       const float* __restrict__ x,
       const float* __restrict__ We1, const float* __restrict__ be1,
       const float* __restrict__ Wn2, const float* __restrict__ bn2,
       const float* __restrict__ Wc2,
       float* __restrict__ out) {
    extern __shared__ float sm[];
    float* Mn_sh  = sm;               // 4096
    float* Mc_sh  = Mn_sh + 4096;     // 4096
    float* Wn2_sh = Mc_sh + 4096;     // 8192
    float* gbuf   = Wn2_sh + 8192;    // 8 warps * 512 = 4096
    float* bn_sh  = gbuf + 4096;      // 128
    float* bc_sh  = bn_sh + 128;      // 128
    float* Wc2_sh = bc_sh + 128;      // 128
    float* bn2_sh = Wc2_sh + 128;     // 64
    float* We1_sh = bn2_sh + 64;      // 32
    float* be1_sh = We1_sh + 32;      // 32

    for (int i = threadIdx.x; i < 4096; i += blockDim.x) {
        Mn_sh[i] = g_Mn[i];
        Mc_sh[i] = g_Mc[i];
    }
    for (int i = threadIdx.x; i < 8192; i += blockDim.x) Wn2_sh[i] = Wn2[i];
    if (threadIdx.x < 128) {
        bn_sh[threadIdx.x]  = g_bn[threadIdx.x];
        bc_sh[threadIdx.x]  = g_bc[threadIdx.x];
        Wc2_sh[threadIdx.x] = Wc2[threadIdx.x];
    }
    if (threadIdx.x < 64) bn2_sh[threadIdx.x] = bn2[threadIdx.x];
    if (threadIdx.x < 32) {
        We1_sh[threadIdx.x] = We1[threadIdx.x];
        be1_sh[threadIdx.x] = be1[threadIdx.x];
    }
    __syncthreads();

    const int lane = threadIdx.x & 31;
    const int wib  = threadIdx.x >> 5;
    const int gw   = blockIdx.x * (blockDim.x >> 5) + wib;
    const int nw   = gridDim.x * (blockDim.x >> 5);

    const float w_e1  = We1_sh[lane];
    const float b_e1v = be1_sh[lane];
    const float4 bn4   = *(const float4*)&bn_sh[4 * lane];
    const float4 bc4   = *(const float4*)&bc_sh[4 * lane];
    const float4 wc2_4 = *(const float4*)&Wc2_sh[4 * lane];
    const float2 bn2_2 = *(const float2*)&bn2_sh[2 * lane];
    float* gb = gbuf + wib * 512;
    const float4* A4 = (const float4*)g_A;
    const float2* W2 = (const float2*)Wn2_sh;
    float* out_x = out + (size_t)N_NODES * 64;

    for (int base = gw * 4; base < N_EDGES; base += nw * 4) {
        int src[4], dstn[4];
        float t[4];
#pragma unroll
        for (int ee = 0; ee < 4; ee++) {
            int e = base + ee;
            float d = 0.f; int s = 0, dd = 0;
            if (e < N_EDGES) { d = dist[e]; s = eidx[e]; dd = eidx[N_EDGES + e]; }
            src[ee] = s; dstn[ee] = dd;
            t[ee] = silu1(d * w_e1 + b_e1v);
        }

        float4 pn[4], pc[4];
#pragma unroll
        for (int ee = 0; ee < 4; ee++) {
            const float4* rs = A4 + (size_t)src[ee]  * 128;
            const float4* rd = A4 + (size_t)dstn[ee] * 128;
            float4 a = rs[lane], b = rd[32 + lane], c = rs[64 + lane], dv = rd[96 + lane];
            pn[ee].x = bn4.x + a.x + b.x;  pn[ee].y = bn4.y + a.y + b.y;
            pn[ee].z = bn4.z + a.z + b.z;  pn[ee].w = bn4.w + a.w + b.w;
            pc[ee].x = bc4.x + c.x + dv.x; pc[ee].y = bc4.y + c.y + dv.y;
            pc[ee].z = bc4.z + c.z + dv.z; pc[ee].w = bc4.w + c.w + dv.w;
        }

#pragma unroll
        for (int k = 0; k < 32; k++) {
            float4 mn = *(const float4*)&Mn_sh[k * 128 + 4 * lane];
            float4 mc = *(const float4*)&Mc_sh[k * 128 + 4 * lane];
#pragma unroll
            for (int ee = 0; ee < 4; ee++) {
                float tk = __shfl_sync(0xffffffffu, t[ee], k);
                pn[ee].x += tk * mn.x; pn[ee].y += tk * mn.y;
                pn[ee].z += tk * mn.z; pn[ee].w += tk * mn.w;
                pc[ee].x += tk * mc.x; pc[ee].y += tk * mc.y;
                pc[ee].z += tk * mc.z; pc[ee].w += tk * mc.w;
            }
        }

        float cw[4];
#pragma unroll
        for (int ee = 0; ee < 4; ee++) {
            float4 gn, gc;
            gn.x = silu1(pn[ee].x); gn.y = silu1(pn[ee].y);
            gn.z = silu1(pn[ee].z); gn.w = silu1(pn[ee].w);
            gc.x = silu1(pc[ee].x); gc.y = silu1(pc[ee].y);
            gc.z = silu1(pc[ee].z); gc.w = silu1(pc[ee].w);
            float s = gc.x * wc2_4.x + gc.y * wc2_4.y + gc.z * wc2_4.z + gc.w * wc2_4.w;
#pragma unroll
            for (int off = 16; off > 0; off >>= 1) s += __shfl_xor_sync(0xffffffffu, s, off);
            cw[ee] = s;
            *(float4*)&gb[ee * 128 + 4 * lane] = gn;
        }
        __syncwarp();

        float2 mac[4];
#pragma unroll
        for (int ee = 0; ee < 4; ee++) mac[ee] = bn2_2;
#pragma unroll
        for (int jc = 0; jc < 32; jc++) {
            float2 w0 = W2[(4 * jc + 0) * 32 + lane];
            float2 w1 = W2[(4 * jc + 1) * 32 + lane];
            float2 w2 = W2[(4 * jc + 2) * 32 + lane];
            float2 w3 = W2[(4 * jc + 3) * 32 + lane];
#pragma unroll
            for (int ee = 0; ee < 4; ee++) {
                float4 g4 = *(const float4*)&gb[ee * 128 + 4 * jc];
                mac[ee].x += g4.x * w0.x + g4.y * w1.x + g4.z * w2.x + g4.w * w3.x;
                mac[ee].y += g4.x * w0.y + g4.y * w1.y + g4.z * w2.y + g4.w * w3.y;
            }
        }

        // scatter node messages
#pragma unroll
        for (int ee = 0; ee < 4; ee++) {
            if (base + ee < N_EDGES) {
                float* oh = out + (size_t)dstn[ee] * 64;
                atomicAdd(&oh[2 * lane],     mac[ee].x);
                atomicAdd(&oh[2 * lane + 1], mac[ee].y);
            }
        }

        // scatter coord updates: lanes 0,8,16,24 handle edges 0..3
        if ((lane & 7) == 0) {
            int ee = lane >> 3;
            if (base + ee < N_EDGES) {
                int s = src[ee], dd = dstn[ee];
                float dx = x[s * 3 + 0] - x[dd * 3 + 0];
                float dy = x[s * 3 + 1] - x[dd * 3 + 1];
                float dz = x[s * 3 + 2] - x[dd * 3 + 2];
                float len = sqrtf(dx * dx + dy * dy + dz * dz);
                len = fmaxf(len, 1e-8f);
                float inv = cw[ee] / len;
                float* ox = out_x + (size_t)dd * 3;
                atomicAdd(&ox[0], dx * inv);
                atomicAdd(&ox[1], dy * inv);
                atomicAdd(&ox[2], dz * inv);
            }
        }
    }
}

// ---------------------------------------------------------------------------
extern "C" void kernel_launch(void* const* d_in, const int* in_sizes, int n_in,
                              void* d_out, int out_size) {
    const float* h    = (const float*)d_in[0];
    const float* x    = (const float*)d_in[1];
    const float* dist = (const float*)d_in[2];
    const float* We1  = (const float*)d_in[3];
    const float* be1  = (const float*)d_in[4];
    const float* We2  = (const float*)d_in[5];
    const float* be2  = (const float*)d_in[6];
    const float* Wn1  = (const float*)d_in[7];
    const float* bn1  = (const float*)d_in[8];
    const float* Wn2  = (const float*)d_in[9];
    const float* bn2  = (const float*)d_in[10];
    const float* Wc1  = (const float*)d_in[11];
    const float* bc1  = (const float*)d_in[12];
    const float* Wc2  = (const float*)d_in[13];
    const int*   eidx = (const int*)d_in[14];
    float* out = (float*)d_out;

    static bool attr_set = false;
    if (!attr_set) {
        cudaFuncSetAttribute(k_edge, cudaFuncAttributeMaxDynamicSharedMemorySize, 84 * 1024);
        attr_set = true;
    }

    k_fold<<<1, 128>>>(We2, be2, Wn1, bn1, Wc1, bc1);
    k_node<<<(N_NODES + NPB - 1) / NPB, 128>>>(h, Wn1, Wc1);
    k_init<<<2048, 256>>>(h, x, out);

    const int smem = 20992 * sizeof(float);  // 83968 B
    k_edge<<<296, 256, smem>>>(dist, eidx, x, We1, be1, Wn2, bn2, Wc2, out);
}

// round 2
// speedup vs baseline: 1.0211x; 1.0211x over previous
#include <cuda_runtime.h>
#include <math.h>

#define N_NODES  50000
#define N_EDGES  800000
#define NODE_DIM 64
#define EDGE_DIM 32
#define HID      128
#define EPB      8

typedef unsigned long long ull;

// Scratch: per-node precomputed rows [ns(128) | nd(128) | cs(128) | cd(128)]
__device__ float g_A[(size_t)N_NODES * 512];
// Folded edge-path weights
__device__ float g_Mn[32 * 128];
__device__ float g_Mc[32 * 128];
__device__ float g_bn[128];
__device__ float g_bc[128];
// Rearranged Wn2: WA[i*32+l] = Wn2[4i..4i+3][2l], WB same for 2l+1
__device__ float4 g_WA[1024];
__device__ float4 g_WB[1024];

union F4 { float4 f; ulonglong2 u; };

__device__ __forceinline__ ull pk2(float x, float y) {
    ull r; asm("mov.b64 %0,{%1,%2};" : "=l"(r) : "f"(x), "f"(y)); return r;
}
__device__ __forceinline__ void upk2(ull v, float& x, float& y) {
    asm("mov.b64 {%0,%1},%2;" : "=f"(x), "=f"(y) : "l"(v));
}
__device__ __forceinline__ ull ffma2(ull a, ull b, ull c) {
    ull d; asm("fma.rn.f32x2 %0,%1,%2,%3;" : "=l"(d) : "l"(a), "l"(b), "l"(c)); return d;
}
__device__ __forceinline__ ull fadd2(ull a, ull b) {
    ull d; asm("add.rn.f32x2 %0,%1,%2;" : "=l"(d) : "l"(a), "l"(b)); return d;
}
__device__ __forceinline__ float silu1(float z) {
    return z * __fdividef(1.f, 1.f + __expf(-z));
}

// ---------------------------------------------------------------------------
// K0: fold edge-path weights + rearrange Wn2
// ---------------------------------------------------------------------------
__global__ void k_fold(const float* __restrict__ We2, const float* __restrict__ be2,
                       const float* __restrict__ Wn1, const float* __restrict__ bn1,
                       const float* __restrict__ Wc1, const float* __restrict__ bc1,
                       const float* __restrict__ Wn2) {
    int j = threadIdx.x;  // 0..127
    float bn = bn1[j], bc = bc1[j];
    for (int b = 0; b < 32; b++) {
        bn += be2[b] * Wn1[(128 + b) * 128 + j];
        bc += be2[b] * Wc1[(128 + b) * 128 + j];
    }
    g_bn[j] = bn;
    g_bc[j] = bc;
    for (int a = 0; a < 32; a++) {
        float sn = 0.f, sc = 0.f;
        for (int b = 0; b < 32; b++) {
            float w = We2[a * 32 + b];
            sn += w * Wn1[(128 + b) * 128 + j];
            sc += w * Wc1[(128 + b) * 128 + j];
        }
        g_Mn[a * 128 + j] = sn;
        g_Mc[a * 128 + j] = sc;
    }
    // Wn2 [128][64] row-major -> WA/WB lane-contiguous float4 along k
    for (int idx = j; idx < 1024; idx += 128) {
        int i = idx >> 5, l = idx & 31;
        g_WA[idx] = make_float4(Wn2[(4 * i + 0) * 64 + 2 * l], Wn2[(4 * i + 1) * 64 + 2 * l],
                                Wn2[(4 * i + 2) * 64 + 2 * l], Wn2[(4 * i + 3) * 64 + 2 * l]);
        g_WB[idx] = make_float4(Wn2[(4 * i + 0) * 64 + 2 * l + 1], Wn2[(4 * i + 1) * 64 + 2 * l + 1],
                                Wn2[(4 * i + 2) * 64 + 2 * l + 1], Wn2[(4 * i + 3) * 64 + 2 * l + 1]);
    }
}

// ---------------------------------------------------------------------------
// K1: per-node precompute  A[n] = [h@Wn1_src | h@Wn1_dst | h@Wc1_src | h@Wc1_dst]
// ---------------------------------------------------------------------------
#define NPB 8
__global__ void k_node(const float* __restrict__ h,
                       const float* __restrict__ Wn1,
                       const float* __restrict__ Wc1) {
    __shared__ float h_sh[NPB * 64];
    int node0 = blockIdx.x * NPB;
    for (int i = threadIdx.x; i < NPB * 64; i += 128) {
        int idx = node0 * 64 + i;
        h_sh[i] = (idx < N_NODES * 64) ? h[idx] : 0.f;
    }
    __syncthreads();
    int j = threadIdx.x;  // 0..127
    float ans[NPB], andv[NPB], acs[NPB], acd[NPB];
#pragma unroll
    for (int n = 0; n < NPB; n++) { ans[n] = 0.f; andv[n] = 0.f; acs[n] = 0.f; acd[n] = 0.f; }
#pragma unroll 4
    for (int k = 0; k < 64; k++) {
        float w0 = Wn1[k * 128 + j];
        float w1 = Wn1[(64 + k) * 128 + j];
        float w2 = Wc1[k * 128 + j];
        float w3 = Wc1[(64 + k) * 128 + j];
#pragma unroll
        for (int n = 0; n < NPB; n++) {
            float hv = h_sh[n * 64 + k];
            ans[n]  += hv * w0;
            andv[n] += hv * w1;
            acs[n]  += hv * w2;
            acd[n]  += hv * w3;
        }
    }
#pragma unroll
    for (int n = 0; n < NPB; n++) {
        int node = node0 + n;
        if (node < N_NODES) {
            size_t base = (size_t)node * 512;
            g_A[base + j]       = ans[n];
            g_A[base + 128 + j] = andv[n];
            g_A[base + 256 + j] = acs[n];
            g_A[base + 384 + j] = acd[n];
        }
    }
}

// ---------------------------------------------------------------------------
// K2: initialize output with (h, x)
// ---------------------------------------------------------------------------
__global__ void k_init(const float* __restrict__ h, const float* __restrict__ x,
                       float* __restrict__ out) {
    int nh = N_NODES * NODE_DIM;
    int tot = nh + N_NODES * 3;
    for (int i = blockIdx.x * blockDim.x + threadIdx.x; i < tot; i += gridDim.x * blockDim.x)
        out[i] = (i < nh) ? h[i] : x[i - nh];
}

// ---------------------------------------------------------------------------
// K3: edge kernel, EPB=8 edges per warp iteration, packed f32x2 math.
// ---------------------------------------------------------------------------
__global__ void __launch_bounds__(256, 2)
k_edge(const float* __restrict__ dist,
       const int*   __restrict__ eidx,
       const float* __restrict__ x,
       const float* __restrict__ We1, const float* __restrict__ be1,
       const float* __restrict__ bn2,
       const float* __restrict__ Wc2,
       float* __restrict__ out) {
    extern __shared__ float sm[];
    float*  Mn_sh = sm;                 // 4096
    float*  Mc_sh = Mn_sh + 4096;       // 4096
    float4* WA_sh = (float4*)(Mc_sh + 4096);   // 1024 f4
    float4* WB_sh = WA_sh + 1024;              // 1024 f4
    float*  gbuf  = (float*)(WB_sh + 1024);    // 8 warps * 1024 = 8192
    float*  bn_sh  = gbuf + 8192;       // 128
    float*  bc_sh  = bn_sh + 128;       // 128
    float*  Wc2_sh = bc_sh + 128;       // 128
    float*  bn2_sh = Wc2_sh + 128;      // 64
    float*  We1_sh = bn2_sh + 64;       // 32
    float*  be1_sh = We1_sh + 32;       // 32

    for (int i = threadIdx.x; i < 4096; i += blockDim.x) {
        Mn_sh[i] = g_Mn[i];
        Mc_sh[i] = g_Mc[i];
    }
    for (int i = threadIdx.x; i < 1024; i += blockDim.x) {
        WA_sh[i] = g_WA[i];
        WB_sh[i] = g_WB[i];
    }
    if (threadIdx.x < 128) {
        bn_sh[threadIdx.x]  = g_bn[threadIdx.x];
        bc_sh[threadIdx.x]  = g_bc[threadIdx.x];
        Wc2_sh[threadIdx.x] = Wc2[threadIdx.x];
    }
    if (threadIdx.x < 64) bn2_sh[threadIdx.x] = bn2[threadIdx.x];
    if (threadIdx.x < 32) {
        We1_sh[threadIdx.x] = We1[threadIdx.x];
        be1_sh[threadIdx.x] = be1[threadIdx.x];
    }
    __syncthreads();

    const int lane = threadIdx.x & 31;
    const int wib  = threadIdx.x >> 5;
    const int gw   = blockIdx.x * (blockDim.x >> 5) + wib;
    const int nw   = gridDim.x * (blockDim.x >> 5);

    const float w_e1  = We1_sh[lane];
    const float b_e1v = be1_sh[lane];
    F4 bn4; bn4.f = *(const float4*)&bn_sh[4 * lane];
    F4 bc4; bc4.f = *(const float4*)&bc_sh[4 * lane];
    F4 wc2_4; wc2_4.f = *(const float4*)&Wc2_sh[4 * lane];
    const float2 bn2_2 = *(const float2*)&bn2_sh[2 * lane];
    float* gb = gbuf + wib * 1024;
    const float4* A4 = (const float4*)g_A;
    const float4* Mn4 = (const float4*)Mn_sh;
    const float4* Mc4 = (const float4*)Mc_sh;
    const float4* gb4 = (const float4*)gb;
    float* out_x = out + (size_t)N_NODES * 64;

    // N_EDGES % EPB == 0 -> all groups full, no bounds checks needed
    for (int base = gw * EPB; base < N_EDGES; base += nw * EPB) {
        int src[EPB], dstn[EPB];
        float t[EPB];
#pragma unroll
        for (int ee = 0; ee < EPB; ee++) {
            int e = base + ee;
            float d = dist[e];
            src[ee]  = eidx[e];
            dstn[ee] = eidx[N_EDGES + e];
            t[ee] = silu1(d * w_e1 + b_e1v);
        }

        // ---- phase pn: node-MLP hidden (128) ----
        ull pnl[EPB], pnh[EPB];
#pragma unroll
        for (int ee = 0; ee < EPB; ee++) {
            F4 a; a.f = A4[(size_t)src[ee]  * 128 + lane];
            F4 b; b.f = A4[(size_t)dstn[ee] * 128 + 32 + lane];
            pnl[ee] = fadd2(fadd2(a.u.x, b.u.x), bn4.u.x);
            pnh[ee] = fadd2(fadd2(a.u.y, b.u.y), bn4.u.y);
        }
#pragma unroll
        for (int k = 0; k < 32; k++) {
            F4 mn; mn.f = Mn4[k * 32 + lane];
#pragma unroll
            for (int ee = 0; ee < EPB; ee++) {
                float tk = __shfl_sync(0xffffffffu, t[ee], k);
                ull tk2 = pk2(tk, tk);
                pnl[ee] = ffma2(tk2, mn.u.x, pnl[ee]);
                pnh[ee] = ffma2(tk2, mn.u.y, pnh[ee]);
            }
        }
#pragma unroll
        for (int ee = 0; ee < EPB; ee++) {
            float p0, p1, p2, p3;
            upk2(pnl[ee], p0, p1);
            upk2(pnh[ee], p2, p3);
            float4 gn = make_float4(silu1(p0), silu1(p1), silu1(p2), silu1(p3));
            *(float4*)&gb[ee * 128 + 4 * lane] = gn;
        }

        // ---- phase pc: coord-MLP hidden (128) -> scalar cw ----
        ull pcl[EPB], pch[EPB];
#pragma unroll
        for (int ee = 0; ee < EPB; ee++) {
            F4 c; c.f = A4[(size_t)src[ee]  * 128 + 64 + lane];
            F4 d; d.f = A4[(size_t)dstn[ee] * 128 + 96 + lane];
            pcl[ee] = fadd2(fadd2(c.u.x, d.u.x), bc4.u.x);
            pch[ee] = fadd2(fadd2(c.u.y, d.u.y), bc4.u.y);
        }
#pragma unroll
        for (int k = 0; k < 32; k++) {
            F4 mc; mc.f = Mc4[k * 32 + lane];
#pragma unroll
            for (int ee = 0; ee < EPB; ee++) {
                float tk = __shfl_sync(0xffffffffu, t[ee], k);
                ull tk2 = pk2(tk, tk);
                pcl[ee] = ffma2(tk2, mc.u.x, pcl[ee]);
                pch[ee] = ffma2(tk2, mc.u.y, pch[ee]);
            }
        }
        float cw[EPB];
#pragma unroll
        for (int ee = 0; ee < EPB; ee++) {
            float p0, p1, p2, p3;
            upk2(pcl[ee], p0, p1);
            upk2(pch[ee], p2, p3);
            float s = silu1(p0) * wc2_4.f.x + silu1(p1) * wc2_4.f.y
                    + silu1(p2) * wc2_4.f.z + silu1(p3) * wc2_4.f.w;
#pragma unroll
            for (int off = 16; off > 0; off >>= 1)
                s += __shfl_xor_sync(0xffffffffu, s, off);
            cw[ee] = s;
        }

        // ---- coord scatter (lanes 0..7, one edge each) ----
        if (lane < EPB) {
            float mycw = cw[0]; int ms = src[0], md = dstn[0];
#pragma unroll
            for (int ee = 1; ee < EPB; ee++)
                if (lane == ee) { mycw = cw[ee]; ms = src[ee]; md = dstn[ee]; }
            float dx = x[ms * 3 + 0] - x[md * 3 + 0];
            float dy = x[ms * 3 + 1] - x[md * 3 + 1];
            float dz = x[ms * 3 + 2] - x[md * 3 + 2];
            float len = fmaxf(sqrtf(dx * dx + dy * dy + dz * dz), 1e-8f);
            float inv = mycw / len;
            float* ox = out_x + (size_t)md * 3;
            atomicAdd(&ox[0], dx * inv);
            atomicAdd(&ox[1], dy * inv);
            atomicAdd(&ox[2], dz * inv);
        }
        __syncwarp();

        // ---- phase 2: gn(128) @ Wn2 -> 64, weights in regs, gn broadcast ----
        ull macA[EPB], macB[EPB];
#pragma unroll
        for (int ee = 0; ee < EPB; ee++) {
            macA[ee] = pk2(bn2_2.x, 0.f);
            macB[ee] = pk2(bn2_2.y, 0.f);
        }
#pragma unroll
        for (int i = 0; i < 32; i++) {
            F4 wA; wA.f = WA_sh[i * 32 + lane];
            F4 wB; wB.f = WB_sh[i * 32 + lane];
#pragma unroll
            for (int ee = 0; ee < EPB; ee++) {
                F4 g; g.f = gb4[ee * 32 + i];  // broadcast
                macA[ee] = ffma2(g.u.x, wA.u.x, macA[ee]);
                macA[ee] = ffma2(g.u.y, wA.u.y, macA[ee]);
                macB[ee] = ffma2(g.u.x, wB.u.x, macB[ee]);
                macB[ee] = ffma2(g.u.y, wB.u.y, macB[ee]);
            }
        }

        // ---- node message scatter ----
#pragma unroll
        for (int ee = 0; ee < EPB; ee++) {
            float a0, a1, b0, b1;
            upk2(macA[ee], a0, a1);
            upk2(macB[ee], b0, b1);
            float* oh = out + (size_t)dstn[ee] * 64;
            atomicAdd(&oh[2 * lane],     a0 + a1);
            atomicAdd(&oh[2 * lane + 1], b0 + b1);
        }
    }
}

// ---------------------------------------------------------------------------
extern "C" void kernel_launch(void* const* d_in, const int* in_sizes, int n_in,
                              void* d_out, int out_size) {
    const float* h    = (const float*)d_in[0];
    const float* x    = (const float*)d_in[1];
    const float* dist = (const float*)d_in[2];
    const float* We1  = (const float*)d_in[3];
    const float* be1  = (const float*)d_in[4];
    const float* We2  = (const float*)d_in[5];
    const float* be2  = (const float*)d_in[6];
    const float* Wn1  = (const float*)d_in[7];
    const float* bn1  = (const float*)d_in[8];
    const float* Wn2  = (const float*)d_in[9];
    const float* bn2  = (const float*)d_in[10];
    const float* Wc1  = (const float*)d_in[11];
    const float* bc1  = (const float*)d_in[12];
    const float* Wc2  = (const float*)d_in[13];
    const int*   eidx = (const int*)d_in[14];
    float* out = (float*)d_out;

    static bool attr_set = false;
    if (!attr_set) {
        cudaFuncSetAttribute(k_edge, cudaFuncAttributeMaxDynamicSharedMemorySize, 101 * 1024);
        attr_set = true;
    }

    k_fold<<<1, 128>>>(We2, be2, Wn1, bn1, Wc1, bc1, Wn2);
    k_node<<<(N_NODES + NPB - 1) / NPB, 128>>>(h, Wn1, Wc1);
    k_init<<<2048, 256>>>(h, x, out);

    const int smem = 25088 * sizeof(float);  // 100352 B
    k_edge<<<296, 256, smem>>>(dist, eidx, x, We1, be1, bn2, Wc2, out);
}